// round 11
// baseline (speedup 1.0000x reference)
#include <cuda_runtime.h>
#include <math.h>

#define B_ 4
#define C_ 128
#define T_ 32
#define H_ 24
#define W_ 24
#define M_ 3
#define HW_ (H_*W_)               // 576
#define NPER (B_*C_*T_*HW_)       // 9437184 elements per output tensor

// Scratch (device globals; no allocation allowed)
__device__ float g_qg[B_*T_*C_];     // [b][t][c]  pooled q
__device__ float g_alpha[B_*M_*T_];  // [b][m][t]  softmax mixture weights

// ---------------------------------------------------------------------------
// Kernel 1: spatial mean pool of q. One WARP per (b,c,t) slice.
// 576 floats = 144 float4; lane loads f4 at lane, +32, +64, +96, (+128 if <16).
// ---------------------------------------------------------------------------
__global__ __launch_bounds__(256) void pool_kernel(const float4* __restrict__ q4) {
    int w = threadIdx.x >> 5, lane = threadIdx.x & 31;
    int idx = blockIdx.x * 8 + w;          // b*C*T + c*T + t
    const float4* p = q4 + (size_t)idx * 144;
    float4 a = p[lane], b4 = p[lane + 32], c4 = p[lane + 64], d4 = p[lane + 96];
    float s = a.x + a.y + a.z + a.w + b4.x + b4.y + b4.z + b4.w
            + c4.x + c4.y + c4.z + c4.w + d4.x + d4.y + d4.z + d4.w;
    if (lane < 16) {
        float4 e = p[lane + 128];
        s += e.x + e.y + e.z + e.w;
    }
    #pragma unroll
    for (int o = 16; o; o >>= 1) s += __shfl_down_sync(0xffffffffu, s, o);
    if (lane == 0) {
        int t = idx % T_, c = (idx / T_) % C_, b = idx / (T_ * C_);
        g_qg[(b * T_ + t) * C_ + c] = s * (1.0f / HW_);
    }
}

// ---------------------------------------------------------------------------
// Kernel 2 (fused): per batch b: h = GELU(pre_w @ qg + pre_b) for all t (kept
// in smem), then causal conv1d C->M + softmax -> alpha[b,m,t]. grid = B_.
// ---------------------------------------------------------------------------
__global__ __launch_bounds__(128) void mix_kernel(const float* __restrict__ pre_w,
                                                  const float* __restrict__ pre_b,
                                                  const float* __restrict__ mix_w,
                                                  const float* __restrict__ mix_b) {
    int b = blockIdx.x, tid = threadIdx.x;
    __shared__ float sq[T_ * C_];
    __shared__ float sh[T_ * C_];
    __shared__ float lg[M_ * T_];

    #pragma unroll
    for (int t = 0; t < T_; ++t) sq[t * C_ + tid] = g_qg[(b * T_ + t) * C_ + tid];
    __syncthreads();

    float acc[T_];
    float pb = pre_b[tid];
    #pragma unroll
    for (int t = 0; t < T_; ++t) acc[t] = pb;
    for (int c = 0; c < C_; ++c) {
        float wv = pre_w[tid * C_ + c];
        #pragma unroll
        for (int t = 0; t < T_; ++t) acc[t] = fmaf(wv, sq[t * C_ + c], acc[t]);
    }
    #pragma unroll
    for (int t = 0; t < T_; ++t) {
        float x = acc[t];
        sh[t * C_ + tid] = 0.5f * x * (1.0f + erff(x * 0.70710678118654752440f));
    }
    __syncthreads();

    if (tid < 96) {
        int m = tid >> 5, t = tid & 31;
        float a = mix_b[m];
        #pragma unroll
        for (int j = 0; j < 3; ++j) {
            int tt = t - 2 + j;
            if (tt >= 0) {
                const float* hp = sh + tt * C_;
                const float* wp = mix_w + m * C_ * 3 + j;
                #pragma unroll 8
                for (int c = 0; c < C_; ++c) a = fmaf(wp[c * 3], hp[c], a);
            }
        }
        lg[m * T_ + t] = a;
    }
    __syncthreads();
    if (tid < T_) {
        int t = tid;
        float l0 = lg[t], l1 = lg[T_ + t], l2 = lg[2 * T_ + t];
        float mx = fmaxf(l0, fmaxf(l1, l2));
        float e0 = expf(l0 - mx), e1 = expf(l1 - mx), e2 = expf(l2 - mx);
        float inv = 1.f / (e0 + e1 + e2);
        g_alpha[(b * M_ + 0) * T_ + t] = e0 * inv;
        g_alpha[(b * M_ + 1) * T_ + t] = e1 * inv;
        g_alpha[(b * M_ + 2) * T_ + t] = e2 * inv;
    }
}

// ---------------------------------------------------------------------------
// Kernel 3: fused mixture depthwise causal 3D conv for BOTH k and v.
// EXACT R9 version (measured 53.6us, 80 regs, no spills): 72 threads,
// per-thread tile 2 rows x 4 cols x 2 timesteps, float4 weight broadcasts
// read inside the loop (NOT hoisted into register arrays).
// ---------------------------------------------------------------------------
#define TT    8
#define RS    28       // padded row stride (floats)
#define SLICE (26*RS)  // 728 floats per padded slice
#define WFSZ  144      // 2 to * 2 tensors * 9 (d,dh) * 4 (dw padded)

__global__ __launch_bounds__(72) void conv_kernel(
    const float* __restrict__ kin, const float* __restrict__ vin,
    const float* __restrict__ Wk,  const float* __restrict__ Wv,
    float* __restrict__ out) {
    __shared__ float sm[8 * SLICE + WFSZ];  // 4 k slices, 4 v slices, weights
    float* wf = sm + 8 * SLICE;             // 16B-aligned (5824 % 4 == 0)

    int t0 = blockIdx.x * TT;
    int c = blockIdx.y, b = blockIdx.z;
    int tid = threadIdx.x;
    int hi = tid / 6, seg = tid % 6;
    int h0 = hi * 2, w0 = seg * 4;
    int lrow = tid / 3, lcol = (tid % 3) * 8;   // loader mapping: 8 floats each

    size_t bc = (size_t)b * C_ + c;
    const float* kbase = kin + bc * T_ * HW_;
    const float* vbase = vin + bc * T_ * HW_;
    float* okbase = out + bc * T_ * HW_;
    float* ovbase = out + (size_t)NPER + bc * T_ * HW_;
    const float* Wkc = Wk + c * 27;
    const float* Wvc = Wv + c * 27;

    // zero all slices (borders + temporal zero padding), vectorized
    for (int i = tid; i < (8 * SLICE) / 4; i += 72)
        ((float4*)sm)[i] = make_float4(0.f, 0.f, 0.f, 0.f);

    __syncthreads();   // zeros fully visible before any data is stored

    // prologue: slices t0-2, t0-1
    #pragma unroll
    for (int s = 0; s < 2; ++s) {
        int tt = t0 - 2 + s;
        if (tt >= 0) {
            int slot = tt & 3;
            const float* gk = kbase + (size_t)tt * HW_ + tid * 8;
            const float* gv = vbase + (size_t)tt * HW_ + tid * 8;
            float4 ka = ((const float4*)gk)[0], kb2 = ((const float4*)gk)[1];
            float4 va = ((const float4*)gv)[0], vb2 = ((const float4*)gv)[1];
            float* dk = sm + slot * SLICE + (lrow + 1) * RS + lcol + 1;
            float* dv = sm + (4 + slot) * SLICE + (lrow + 1) * RS + lcol + 1;
            dk[0]=ka.x; dk[1]=ka.y; dk[2]=ka.z; dk[3]=ka.w;
            dk[4]=kb2.x; dk[5]=kb2.y; dk[6]=kb2.z; dk[7]=kb2.w;
            dv[0]=va.x; dv[1]=va.y; dv[2]=va.z; dv[3]=va.w;
            dv[4]=vb2.x; dv[5]=vb2.y; dv[6]=vb2.z; dv[7]=vb2.w;
        }
    }

    #pragma unroll 1
    for (int p = 0; p < TT / 2; ++p) {
        int t = t0 + 2 * p;
        __syncthreads();   // previous pair's reads done before slot overwrite
        // load slices t, t+1 (always in range)
        #pragma unroll
        for (int s = 0; s < 2; ++s) {
            int tt = t + s;
            int slot = tt & 3;
            const float* gk = kbase + (size_t)tt * HW_ + tid * 8;
            const float* gv = vbase + (size_t)tt * HW_ + tid * 8;
            float4 ka = ((const float4*)gk)[0], kb2 = ((const float4*)gk)[1];
            float4 va = ((const float4*)gv)[0], vb2 = ((const float4*)gv)[1];
            float* dk = sm + slot * SLICE + (lrow + 1) * RS + lcol + 1;
            float* dv = sm + (4 + slot) * SLICE + (lrow + 1) * RS + lcol + 1;
            dk[0]=ka.x; dk[1]=ka.y; dk[2]=ka.z; dk[3]=ka.w;
            dk[4]=kb2.x; dk[5]=kb2.y; dk[6]=kb2.z; dk[7]=kb2.w;
            dv[0]=va.x; dv[1]=va.y; dv[2]=va.z; dv[3]=va.w;
            dv[4]=vb2.x; dv[5]=vb2.y; dv[6]=vb2.z; dv[7]=vb2.w;
        }
        // effective weights, padded layout: wf[((to*2+tensor)*9 + d*3+dh)*4 + dw]
        for (int idx = tid; idx < WFSZ; idx += 72) {
            int g = idx >> 2, dw = idx & 3;
            int to = g / 18, r2 = g % 18;
            int tensor = r2 / 9, qd = r2 % 9;
            int d = qd / 3, dh = qd % 3;
            int j = d * 9 + dh * 3 + dw;
            float val = 0.f;
            if (dw < 3) {
                int tt = t + to;
                float a0 = g_alpha[(b * M_ + 0) * T_ + tt];
                float a1 = g_alpha[(b * M_ + 1) * T_ + tt];
                float a2 = g_alpha[(b * M_ + 2) * T_ + tt];
                const float* Wc = tensor ? Wvc : Wkc;
                val = a0 * Wc[j] + a1 * Wc[C_ * 27 + j] + a2 * Wc[2 * C_ * 27 + j];
            }
            wf[idx] = val;
        }
        __syncthreads();

        float ak[2][2][4], av[2][2][4];
        #pragma unroll
        for (int i = 0; i < 2; ++i)
            #pragma unroll
            for (int r = 0; r < 2; ++r)
                #pragma unroll
                for (int wi = 0; wi < 4; ++wi) { ak[i][r][wi] = 0.f; av[i][r][wi] = 0.f; }

        #pragma unroll
        for (int si = 0; si < 4; ++si) {
            int slot = (t - 2 + si) & 3;  // -2&3=2, -1&3=3: correct mod-4
            const float* skb = sm + slot * SLICE;
            const float* svb = sm + (4 + slot) * SLICE;
            #pragma unroll
            for (int ri = 0; ri < 4; ++ri) {
                const float* rkp = skb + (h0 + ri) * RS + w0;  // aligned float4
                float4 f0 = ((const float4*)rkp)[0], f1 = ((const float4*)rkp)[1];
                float rowk[8] = {f0.x,f0.y,f0.z,f0.w,f1.x,f1.y,f1.z,f1.w};
                const float* rvp = svb + (h0 + ri) * RS + w0;
                float4 g0 = ((const float4*)rvp)[0], g1 = ((const float4*)rvp)[1];
                float rowv[8] = {g0.x,g0.y,g0.z,g0.w,g1.x,g1.y,g1.z,g1.w};
                #pragma unroll
                for (int to = 0; to < 2; ++to) {
                    int d = si - to;
                    if (d < 0 || d > 2) continue;       // compile-time after unroll
                    #pragma unroll
                    for (int r = 0; r < 2; ++r) {
                        int dh = ri - r;
                        if (dh < 0 || dh > 2) continue; // compile-time after unroll
                        float4 wk4 = *(const float4*)&wf[((to * 2 + 0) * 9 + d * 3 + dh) * 4];
                        float4 wv4 = *(const float4*)&wf[((to * 2 + 1) * 9 + d * 3 + dh) * 4];
                        float wkk[3] = {wk4.x, wk4.y, wk4.z};
                        float wvv[3] = {wv4.x, wv4.y, wv4.z};
                        #pragma unroll
                        for (int dw = 0; dw < 3; ++dw) {
                            #pragma unroll
                            for (int wi = 0; wi < 4; ++wi) {
                                ak[to][r][wi] = fmaf(wkk[dw], rowk[wi + dw], ak[to][r][wi]);
                                av[to][r][wi] = fmaf(wvv[dw], rowv[wi + dw], av[to][r][wi]);
                            }
                        }
                    }
                }
            }
        }
        #pragma unroll
        for (int to = 0; to < 2; ++to)
            #pragma unroll
            for (int r = 0; r < 2; ++r) {
                size_t off = (size_t)(t + to) * HW_ + (h0 + r) * W_ + w0;
                ((float4*)(okbase + off))[0] =
                    make_float4(ak[to][r][0], ak[to][r][1], ak[to][r][2], ak[to][r][3]);
                ((float4*)(ovbase + off))[0] =
                    make_float4(av[to][r][0], av[to][r][1], av[to][r][2], av[to][r][3]);
            }
    }
}

// ---------------------------------------------------------------------------
// Launch. inputs: 0=q 1=k 2=v 3=Wk 4=Wv 5=pre_w 6=pre_b 7=mix_w 8=mix_b
// ---------------------------------------------------------------------------
extern "C" void kernel_launch(void* const* d_in, const int* in_sizes, int n_in,
                              void* d_out, int out_size) {
    const float* q     = (const float*)d_in[0];
    const float* k     = (const float*)d_in[1];
    const float* v     = (const float*)d_in[2];
    const float* Wk    = (const float*)d_in[3];
    const float* Wv    = (const float*)d_in[4];
    const float* pre_w = (const float*)d_in[5];
    const float* pre_b = (const float*)d_in[6];
    const float* mix_w = (const float*)d_in[7];
    const float* mix_b = (const float*)d_in[8];
    float* out = (float*)d_out;

    pool_kernel<<<(B_ * C_ * T_) / 8, 256>>>((const float4*)q);
    mix_kernel<<<B_, 128>>>(pre_w, pre_b, mix_w, mix_b);
    {
        dim3 g(T_ / TT, C_, B_);
        conv_kernel<<<g, 72>>>(k, v, Wk, Wv, out);
    }
}

// round 12
// speedup vs baseline: 1.0980x; 1.0980x over previous
#include <cuda_runtime.h>
#include <math.h>

#define B_ 4
#define C_ 128
#define T_ 32
#define H_ 24
#define W_ 24
#define M_ 3
#define HW_ (H_*W_)               // 576
#define NPER (B_*C_*T_*HW_)       // 9437184 elements per output tensor

// Scratch (device globals; no allocation allowed)
__device__ float g_qg[B_*T_*C_];     // [b][t][c]  pooled q
__device__ float g_alpha[B_*M_*T_];  // [b][m][t]  softmax mixture weights

// ---------------------------------------------------------------------------
// Kernel 1: spatial mean pool of q. One WARP per (b,c,t) slice. (measured 9.3us)
// ---------------------------------------------------------------------------
__global__ __launch_bounds__(256) void pool_kernel(const float4* __restrict__ q4) {
    int w = threadIdx.x >> 5, lane = threadIdx.x & 31;
    int idx = blockIdx.x * 8 + w;          // b*C*T + c*T + t
    const float4* p = q4 + (size_t)idx * 144;
    float4 a = p[lane], b4 = p[lane + 32], c4 = p[lane + 64], d4 = p[lane + 96];
    float s = a.x + a.y + a.z + a.w + b4.x + b4.y + b4.z + b4.w
            + c4.x + c4.y + c4.z + c4.w + d4.x + d4.y + d4.z + d4.w;
    if (lane < 16) {
        float4 e = p[lane + 128];
        s += e.x + e.y + e.z + e.w;
    }
    #pragma unroll
    for (int o = 16; o; o >>= 1) s += __shfl_down_sync(0xffffffffu, s, o);
    if (lane == 0) {
        int t = idx % T_, c = (idx / T_) % C_, b = idx / (T_ * C_);
        g_qg[(b * T_ + t) * C_ + c] = s * (1.0f / HW_);
    }
}

// ---------------------------------------------------------------------------
// Kernel 2 (fused, parallelized): per batch b.
//  Stage qg + mix_w(transposed) in smem.
//  Matmul split across 2 thread-groups over the c dimension (2048 serial FMA
//  per thread instead of 4096), float4 loads everywhere, smem reduction.
//  Then GELU, causal conv1d C->M (unit-stride smem), softmax -> alpha.
// grid = B_, 256 threads.
// ---------------------------------------------------------------------------
__global__ __launch_bounds__(256) void mix_kernel(const float* __restrict__ pre_w,
                                                  const float* __restrict__ pre_b,
                                                  const float* __restrict__ mix_w,
                                                  const float* __restrict__ mix_b) {
    int b = blockIdx.x, tid = threadIdx.x;
    __shared__ float sq[T_ * C_];          // qg, later reused for partial sums
    __shared__ float sh[T_ * C_];          // GELU output
    __shared__ float wsm[M_ * 3 * C_];     // mix_w transposed: [m][j][c]
    __shared__ float lg[M_ * T_];

    // load qg coalesced as float4
    const float4* qg4 = (const float4*)(g_qg + b * T_ * C_);
    #pragma unroll
    for (int i = tid; i < (T_ * C_) / 4; i += 256) ((float4*)sq)[i] = qg4[i];
    // stage mix_w transposed: wsm[(m*3+j)*C + c] = mix_w[(m*C + c)*3 + j]
    for (int i = tid; i < M_ * C_ * 3; i += 256) {
        int m = i / (C_ * 3), r = i % (C_ * 3);
        int cc = r / 3, j = r % 3;
        wsm[(m * 3 + j) * C_ + cc] = mix_w[i];
    }
    __syncthreads();

    int o = tid & 127, grp = tid >> 7;     // grp0: c 0..63, grp1: c 64..127
    float acc[T_];
    #pragma unroll
    for (int t = 0; t < T_; ++t) acc[t] = 0.f;

    const float4* wrow = (const float4*)(pre_w + o * C_) + grp * 16;
    #pragma unroll 4
    for (int c4 = 0; c4 < 16; ++c4) {
        float4 wv = wrow[c4];
        int cbase = grp * 64 + c4 * 4;
        #pragma unroll
        for (int t = 0; t < T_; ++t) {
            float4 sv = *(const float4*)&sq[t * C_ + cbase];
            acc[t] = fmaf(wv.x, sv.x,
                     fmaf(wv.y, sv.y,
                     fmaf(wv.z, sv.z,
                     fmaf(wv.w, sv.w, acc[t]))));
        }
    }
    __syncthreads();            // all reads of sq done
    if (grp == 1) {
        #pragma unroll
        for (int t = 0; t < T_; ++t) sq[t * C_ + o] = acc[t];   // partials
    }
    __syncthreads();
    if (grp == 0) {
        float pb = pre_b[o];
        #pragma unroll
        for (int t = 0; t < T_; ++t) {
            float x = acc[t] + sq[t * C_ + o] + pb;
            sh[t * C_ + o] = 0.5f * x * (1.0f + erff(x * 0.70710678118654752440f));
        }
    }
    __syncthreads();

    if (tid < 96) {
        int m = tid >> 5, t = tid & 31;
        float a = mix_b[m];
        #pragma unroll
        for (int j = 0; j < 3; ++j) {
            int tt = t - 2 + j;
            if (tt >= 0) {
                const float* hp = sh + tt * C_;
                const float* wp = wsm + (m * 3 + j) * C_;
                #pragma unroll 8
                for (int c = 0; c < C_; ++c) a = fmaf(wp[c], hp[c], a);
            }
        }
        lg[m * T_ + t] = a;
    }
    __syncthreads();
    if (tid < T_) {
        int t = tid;
        float l0 = lg[t], l1 = lg[T_ + t], l2 = lg[2 * T_ + t];
        float mx = fmaxf(l0, fmaxf(l1, l2));
        float e0 = expf(l0 - mx), e1 = expf(l1 - mx), e2 = expf(l2 - mx);
        float inv = 1.f / (e0 + e1 + e2);
        g_alpha[(b * M_ + 0) * T_ + t] = e0 * inv;
        g_alpha[(b * M_ + 1) * T_ + t] = e1 * inv;
        g_alpha[(b * M_ + 2) * T_ + t] = e2 * inv;
    }
}

// ---------------------------------------------------------------------------
// Kernel 3: fused mixture depthwise causal 3D conv for BOTH k and v.
// EXACT R9/R11 version (measured 53.6us): 72 threads, per-thread tile
// 2 rows x 4 cols x 2 timesteps, float4 weight broadcasts in-loop.
// ---------------------------------------------------------------------------
#define TT    8
#define RS    28       // padded row stride (floats)
#define SLICE (26*RS)  // 728 floats per padded slice
#define WFSZ  144      // 2 to * 2 tensors * 9 (d,dh) * 4 (dw padded)

__global__ __launch_bounds__(72) void conv_kernel(
    const float* __restrict__ kin, const float* __restrict__ vin,
    const float* __restrict__ Wk,  const float* __restrict__ Wv,
    float* __restrict__ out) {
    __shared__ float sm[8 * SLICE + WFSZ];  // 4 k slices, 4 v slices, weights
    float* wf = sm + 8 * SLICE;             // 16B-aligned (5824 % 4 == 0)

    int t0 = blockIdx.x * TT;
    int c = blockIdx.y, b = blockIdx.z;
    int tid = threadIdx.x;
    int hi = tid / 6, seg = tid % 6;
    int h0 = hi * 2, w0 = seg * 4;
    int lrow = tid / 3, lcol = (tid % 3) * 8;   // loader mapping: 8 floats each

    size_t bc = (size_t)b * C_ + c;
    const float* kbase = kin + bc * T_ * HW_;
    const float* vbase = vin + bc * T_ * HW_;
    float* okbase = out + bc * T_ * HW_;
    float* ovbase = out + (size_t)NPER + bc * T_ * HW_;
    const float* Wkc = Wk + c * 27;
    const float* Wvc = Wv + c * 27;

    // zero all slices (borders + temporal zero padding), vectorized
    for (int i = tid; i < (8 * SLICE) / 4; i += 72)
        ((float4*)sm)[i] = make_float4(0.f, 0.f, 0.f, 0.f);

    __syncthreads();   // zeros fully visible before any data is stored

    // prologue: slices t0-2, t0-1
    #pragma unroll
    for (int s = 0; s < 2; ++s) {
        int tt = t0 - 2 + s;
        if (tt >= 0) {
            int slot = tt & 3;
            const float* gk = kbase + (size_t)tt * HW_ + tid * 8;
            const float* gv = vbase + (size_t)tt * HW_ + tid * 8;
            float4 ka = ((const float4*)gk)[0], kb2 = ((const float4*)gk)[1];
            float4 va = ((const float4*)gv)[0], vb2 = ((const float4*)gv)[1];
            float* dk = sm + slot * SLICE + (lrow + 1) * RS + lcol + 1;
            float* dv = sm + (4 + slot) * SLICE + (lrow + 1) * RS + lcol + 1;
            dk[0]=ka.x; dk[1]=ka.y; dk[2]=ka.z; dk[3]=ka.w;
            dk[4]=kb2.x; dk[5]=kb2.y; dk[6]=kb2.z; dk[7]=kb2.w;
            dv[0]=va.x; dv[1]=va.y; dv[2]=va.z; dv[3]=va.w;
            dv[4]=vb2.x; dv[5]=vb2.y; dv[6]=vb2.z; dv[7]=vb2.w;
        }
    }

    #pragma unroll 1
    for (int p = 0; p < TT / 2; ++p) {
        int t = t0 + 2 * p;
        __syncthreads();   // previous pair's reads done before slot overwrite
        // load slices t, t+1 (always in range)
        #pragma unroll
        for (int s = 0; s < 2; ++s) {
            int tt = t + s;
            int slot = tt & 3;
            const float* gk = kbase + (size_t)tt * HW_ + tid * 8;
            const float* gv = vbase + (size_t)tt * HW_ + tid * 8;
            float4 ka = ((const float4*)gk)[0], kb2 = ((const float4*)gk)[1];
            float4 va = ((const float4*)gv)[0], vb2 = ((const float4*)gv)[1];
            float* dk = sm + slot * SLICE + (lrow + 1) * RS + lcol + 1;
            float* dv = sm + (4 + slot) * SLICE + (lrow + 1) * RS + lcol + 1;
            dk[0]=ka.x; dk[1]=ka.y; dk[2]=ka.z; dk[3]=ka.w;
            dk[4]=kb2.x; dk[5]=kb2.y; dk[6]=kb2.z; dk[7]=kb2.w;
            dv[0]=va.x; dv[1]=va.y; dv[2]=va.z; dv[3]=va.w;
            dv[4]=vb2.x; dv[5]=vb2.y; dv[6]=vb2.z; dv[7]=vb2.w;
        }
        // effective weights, padded layout: wf[((to*2+tensor)*9 + d*3+dh)*4 + dw]
        for (int idx = tid; idx < WFSZ; idx += 72) {
            int g = idx >> 2, dw = idx & 3;
            int to = g / 18, r2 = g % 18;
            int tensor = r2 / 9, qd = r2 % 9;
            int d = qd / 3, dh = qd % 3;
            int j = d * 9 + dh * 3 + dw;
            float val = 0.f;
            if (dw < 3) {
                int tt = t + to;
                float a0 = g_alpha[(b * M_ + 0) * T_ + tt];
                float a1 = g_alpha[(b * M_ + 1) * T_ + tt];
                float a2 = g_alpha[(b * M_ + 2) * T_ + tt];
                const float* Wc = tensor ? Wvc : Wkc;
                val = a0 * Wc[j] + a1 * Wc[C_ * 27 + j] + a2 * Wc[2 * C_ * 27 + j];
            }
            wf[idx] = val;
        }
        __syncthreads();

        float ak[2][2][4], av[2][2][4];
        #pragma unroll
        for (int i = 0; i < 2; ++i)
            #pragma unroll
            for (int r = 0; r < 2; ++r)
                #pragma unroll
                for (int wi = 0; wi < 4; ++wi) { ak[i][r][wi] = 0.f; av[i][r][wi] = 0.f; }

        #pragma unroll
        for (int si = 0; si < 4; ++si) {
            int slot = (t - 2 + si) & 3;  // -2&3=2, -1&3=3: correct mod-4
            const float* skb = sm + slot * SLICE;
            const float* svb = sm + (4 + slot) * SLICE;
            #pragma unroll
            for (int ri = 0; ri < 4; ++ri) {
                const float* rkp = skb + (h0 + ri) * RS + w0;  // aligned float4
                float4 f0 = ((const float4*)rkp)[0], f1 = ((const float4*)rkp)[1];
                float rowk[8] = {f0.x,f0.y,f0.z,f0.w,f1.x,f1.y,f1.z,f1.w};
                const float* rvp = svb + (h0 + ri) * RS + w0;
                float4 g0 = ((const float4*)rvp)[0], g1 = ((const float4*)rvp)[1];
                float rowv[8] = {g0.x,g0.y,g0.z,g0.w,g1.x,g1.y,g1.z,g1.w};
                #pragma unroll
                for (int to = 0; to < 2; ++to) {
                    int d = si - to;
                    if (d < 0 || d > 2) continue;       // compile-time after unroll
                    #pragma unroll
                    for (int r = 0; r < 2; ++r) {
                        int dh = ri - r;
                        if (dh < 0 || dh > 2) continue; // compile-time after unroll
                        float4 wk4 = *(const float4*)&wf[((to * 2 + 0) * 9 + d * 3 + dh) * 4];
                        float4 wv4 = *(const float4*)&wf[((to * 2 + 1) * 9 + d * 3 + dh) * 4];
                        float wkk[3] = {wk4.x, wk4.y, wk4.z};
                        float wvv[3] = {wv4.x, wv4.y, wv4.z};
                        #pragma unroll
                        for (int dw = 0; dw < 3; ++dw) {
                            #pragma unroll
                            for (int wi = 0; wi < 4; ++wi) {
                                ak[to][r][wi] = fmaf(wkk[dw], rowk[wi + dw], ak[to][r][wi]);
                                av[to][r][wi] = fmaf(wvv[dw], rowv[wi + dw], av[to][r][wi]);
                            }
                        }
                    }
                }
            }
        }
        #pragma unroll
        for (int to = 0; to < 2; ++to)
            #pragma unroll
            for (int r = 0; r < 2; ++r) {
                size_t off = (size_t)(t + to) * HW_ + (h0 + r) * W_ + w0;
                ((float4*)(okbase + off))[0] =
                    make_float4(ak[to][r][0], ak[to][r][1], ak[to][r][2], ak[to][r][3]);
                ((float4*)(ovbase + off))[0] =
                    make_float4(av[to][r][0], av[to][r][1], av[to][r][2], av[to][r][3]);
            }
    }
}

// ---------------------------------------------------------------------------
// Launch. inputs: 0=q 1=k 2=v 3=Wk 4=Wv 5=pre_w 6=pre_b 7=mix_w 8=mix_b
// ---------------------------------------------------------------------------
extern "C" void kernel_launch(void* const* d_in, const int* in_sizes, int n_in,
                              void* d_out, int out_size) {
    const float* q     = (const float*)d_in[0];
    const float* k     = (const float*)d_in[1];
    const float* v     = (const float*)d_in[2];
    const float* Wk    = (const float*)d_in[3];
    const float* Wv    = (const float*)d_in[4];
    const float* pre_w = (const float*)d_in[5];
    const float* pre_b = (const float*)d_in[6];
    const float* mix_w = (const float*)d_in[7];
    const float* mix_b = (const float*)d_in[8];
    float* out = (float*)d_out;

    pool_kernel<<<(B_ * C_ * T_) / 8, 256>>>((const float4*)q);
    mix_kernel<<<B_, 256>>>(pre_w, pre_b, mix_w, mix_b);
    {
        dim3 g(T_ / TT, C_, B_);
        conv_kernel<<<g, 72>>>(k, v, Wk, Wv, out);
    }
}

// round 13
// speedup vs baseline: 1.2480x; 1.1366x over previous
#include <cuda_runtime.h>
#include <math.h>

#define B_ 4
#define C_ 128
#define T_ 32
#define H_ 24
#define W_ 24
#define M_ 3
#define HW_ (H_*W_)               // 576
#define NPER (B_*C_*T_*HW_)       // 9437184 elements per output tensor

// Scratch (device globals; no allocation allowed)
__device__ float g_qg[B_*T_*C_];     // [b][t][c]  pooled q
__device__ float g_alpha[B_*M_*T_];  // [b][m][t]  softmax mixture weights

// ---------------------------------------------------------------------------
// Kernel 1: spatial mean pool of q. One WARP per (b,c,t) slice. (measured 9.6us)
// ---------------------------------------------------------------------------
__global__ __launch_bounds__(256) void pool_kernel(const float4* __restrict__ q4) {
    int w = threadIdx.x >> 5, lane = threadIdx.x & 31;
    int idx = blockIdx.x * 8 + w;          // b*C*T + c*T + t
    const float4* p = q4 + (size_t)idx * 144;
    float4 a = p[lane], b4 = p[lane + 32], c4 = p[lane + 64], d4 = p[lane + 96];
    float s = a.x + a.y + a.z + a.w + b4.x + b4.y + b4.z + b4.w
            + c4.x + c4.y + c4.z + c4.w + d4.x + d4.y + d4.z + d4.w;
    if (lane < 16) {
        float4 e = p[lane + 128];
        s += e.x + e.y + e.z + e.w;
    }
    #pragma unroll
    for (int o = 16; o; o >>= 1) s += __shfl_down_sync(0xffffffffu, s, o);
    if (lane == 0) {
        int t = idx % T_, c = (idx / T_) % C_, b = idx / (T_ * C_);
        g_qg[(b * T_ + t) * C_ + c] = s * (1.0f / HW_);
    }
}

// ---------------------------------------------------------------------------
// Kernel 2 (parallelized 16 blocks): grid (B, 4). Each block owns 8 output
// timesteps and recomputes the 2-timestep causal halo locally (10 h-rows).
// Matmul c-split across 2 thread-groups; conv1d tail uses 4 independent
// accumulators to shorten the dependent-FMA chain.
// ---------------------------------------------------------------------------
__global__ __launch_bounds__(256) void mix_kernel(const float* __restrict__ pre_w,
                                                  const float* __restrict__ pre_b,
                                                  const float* __restrict__ mix_w,
                                                  const float* __restrict__ mix_b) {
    int b = blockIdx.x, tg = blockIdx.y, tid = threadIdx.x;
    const int T0 = tg * 8;
    __shared__ float sq[10 * C_];          // qg rows T0-2..T0+7 (later: partials)
    __shared__ float sh[10 * C_];          // GELU output rows
    __shared__ float wsm[M_ * 3 * C_];     // mix_w transposed: [m][j][c]
    __shared__ float lg[M_ * 8];

    // load qg rows (zero-fill out-of-range halo rows)
    for (int i = tid; i < 10 * (C_ / 4); i += 256) {
        int row = i / (C_ / 4), c4i = i % (C_ / 4);
        int tt = T0 - 2 + row;
        float4 val = make_float4(0.f, 0.f, 0.f, 0.f);
        if (tt >= 0) val = ((const float4*)(g_qg + (b * T_ + tt) * C_))[c4i];
        ((float4*)sq)[i] = val;
    }
    // stage mix_w transposed: wsm[(m*3+j)*C + c] = mix_w[(m*C + c)*3 + j]
    for (int i = tid; i < M_ * C_ * 3; i += 256) {
        int m = i / (C_ * 3), r = i % (C_ * 3);
        int cc = r / 3, j = r % 3;
        wsm[(m * 3 + j) * C_ + cc] = mix_w[i];
    }
    __syncthreads();

    int o = tid & 127, grp = tid >> 7;     // grp0: c 0..63, grp1: c 64..127
    float acc[10];
    #pragma unroll
    for (int i = 0; i < 10; ++i) acc[i] = 0.f;

    const float4* wrow = (const float4*)(pre_w + o * C_) + grp * 16;
    #pragma unroll 4
    for (int c4 = 0; c4 < 16; ++c4) {
        float4 wv = wrow[c4];
        int cbase = grp * 64 + c4 * 4;
        #pragma unroll
        for (int i = 0; i < 10; ++i) {
            float4 sv = *(const float4*)&sq[i * C_ + cbase];
            acc[i] = fmaf(wv.x, sv.x,
                     fmaf(wv.y, sv.y,
                     fmaf(wv.z, sv.z,
                     fmaf(wv.w, sv.w, acc[i]))));
        }
    }
    __syncthreads();            // all reads of sq done
    if (grp == 1) {
        #pragma unroll
        for (int i = 0; i < 10; ++i) sq[i * C_ + o] = acc[i];   // partials
    }
    __syncthreads();
    if (grp == 0) {
        float pb = pre_b[o];
        #pragma unroll
        for (int i = 0; i < 10; ++i) {
            float x = acc[i] + sq[i * C_ + o] + pb;
            sh[i * C_ + o] = 0.5f * x * (1.0f + erff(x * 0.70710678118654752440f));
        }
    }
    __syncthreads();

    // conv1d: 24 threads, thread = (m, local t). h row for tt=t-2+j is local
    // row (tl + j). 4 independent accumulators shorten the dependent chain.
    if (tid < 24) {
        int m = tid / 8, tl = tid % 8;
        float a0 = mix_b[m], a1 = 0.f, a2 = 0.f, a3 = 0.f;
        #pragma unroll
        for (int j = 0; j < 3; ++j) {
            int tt = T0 + tl - 2 + j;
            if (tt >= 0) {
                const float* hp = sh + (tl + j) * C_;
                const float* wp = wsm + (m * 3 + j) * C_;
                #pragma unroll 4
                for (int c = 0; c < C_; c += 4) {
                    a0 = fmaf(wp[c],     hp[c],     a0);
                    a1 = fmaf(wp[c + 1], hp[c + 1], a1);
                    a2 = fmaf(wp[c + 2], hp[c + 2], a2);
                    a3 = fmaf(wp[c + 3], hp[c + 3], a3);
                }
            }
        }
        lg[m * 8 + tl] = (a0 + a1) + (a2 + a3);
    }
    __syncthreads();
    if (tid < 8) {
        int t = T0 + tid;
        float l0 = lg[tid], l1 = lg[8 + tid], l2 = lg[16 + tid];
        float mx = fmaxf(l0, fmaxf(l1, l2));
        float e0 = expf(l0 - mx), e1 = expf(l1 - mx), e2 = expf(l2 - mx);
        float inv = 1.f / (e0 + e1 + e2);
        g_alpha[(b * M_ + 0) * T_ + t] = e0 * inv;
        g_alpha[(b * M_ + 1) * T_ + t] = e1 * inv;
        g_alpha[(b * M_ + 2) * T_ + t] = e2 * inv;
    }
}

// ---------------------------------------------------------------------------
// Kernel 3: fused mixture depthwise causal 3D conv for BOTH k and v.
// EXACT R9/R11 version (measured 53.6us): 72 threads, per-thread tile
// 2 rows x 4 cols x 2 timesteps, float4 weight broadcasts in-loop.
// ---------------------------------------------------------------------------
#define TT    8
#define RS    28       // padded row stride (floats)
#define SLICE (26*RS)  // 728 floats per padded slice
#define WFSZ  144      // 2 to * 2 tensors * 9 (d,dh) * 4 (dw padded)

__global__ __launch_bounds__(72) void conv_kernel(
    const float* __restrict__ kin, const float* __restrict__ vin,
    const float* __restrict__ Wk,  const float* __restrict__ Wv,
    float* __restrict__ out) {
    __shared__ float sm[8 * SLICE + WFSZ];  // 4 k slices, 4 v slices, weights
    float* wf = sm + 8 * SLICE;             // 16B-aligned (5824 % 4 == 0)

    int t0 = blockIdx.x * TT;
    int c = blockIdx.y, b = blockIdx.z;
    int tid = threadIdx.x;
    int hi = tid / 6, seg = tid % 6;
    int h0 = hi * 2, w0 = seg * 4;
    int lrow = tid / 3, lcol = (tid % 3) * 8;   // loader mapping: 8 floats each

    size_t bc = (size_t)b * C_ + c;
    const float* kbase = kin + bc * T_ * HW_;
    const float* vbase = vin + bc * T_ * HW_;
    float* okbase = out + bc * T_ * HW_;
    float* ovbase = out + (size_t)NPER + bc * T_ * HW_;
    const float* Wkc = Wk + c * 27;
    const float* Wvc = Wv + c * 27;

    // zero all slices (borders + temporal zero padding), vectorized
    for (int i = tid; i < (8 * SLICE) / 4; i += 72)
        ((float4*)sm)[i] = make_float4(0.f, 0.f, 0.f, 0.f);

    __syncthreads();   // zeros fully visible before any data is stored

    // prologue: slices t0-2, t0-1
    #pragma unroll
    for (int s = 0; s < 2; ++s) {
        int tt = t0 - 2 + s;
        if (tt >= 0) {
            int slot = tt & 3;
            const float* gk = kbase + (size_t)tt * HW_ + tid * 8;
            const float* gv = vbase + (size_t)tt * HW_ + tid * 8;
            float4 ka = ((const float4*)gk)[0], kb2 = ((const float4*)gk)[1];
            float4 va = ((const float4*)gv)[0], vb2 = ((const float4*)gv)[1];
            float* dk = sm + slot * SLICE + (lrow + 1) * RS + lcol + 1;
            float* dv = sm + (4 + slot) * SLICE + (lrow + 1) * RS + lcol + 1;
            dk[0]=ka.x; dk[1]=ka.y; dk[2]=ka.z; dk[3]=ka.w;
            dk[4]=kb2.x; dk[5]=kb2.y; dk[6]=kb2.z; dk[7]=kb2.w;
            dv[0]=va.x; dv[1]=va.y; dv[2]=va.z; dv[3]=va.w;
            dv[4]=vb2.x; dv[5]=vb2.y; dv[6]=vb2.z; dv[7]=vb2.w;
        }
    }

    #pragma unroll 1
    for (int p = 0; p < TT / 2; ++p) {
        int t = t0 + 2 * p;
        __syncthreads();   // previous pair's reads done before slot overwrite
        // load slices t, t+1 (always in range)
        #pragma unroll
        for (int s = 0; s < 2; ++s) {
            int tt = t + s;
            int slot = tt & 3;
            const float* gk = kbase + (size_t)tt * HW_ + tid * 8;
            const float* gv = vbase + (size_t)tt * HW_ + tid * 8;
            float4 ka = ((const float4*)gk)[0], kb2 = ((const float4*)gk)[1];
            float4 va = ((const float4*)gv)[0], vb2 = ((const float4*)gv)[1];
            float* dk = sm + slot * SLICE + (lrow + 1) * RS + lcol + 1;
            float* dv = sm + (4 + slot) * SLICE + (lrow + 1) * RS + lcol + 1;
            dk[0]=ka.x; dk[1]=ka.y; dk[2]=ka.z; dk[3]=ka.w;
            dk[4]=kb2.x; dk[5]=kb2.y; dk[6]=kb2.z; dk[7]=kb2.w;
            dv[0]=va.x; dv[1]=va.y; dv[2]=va.z; dv[3]=va.w;
            dv[4]=vb2.x; dv[5]=vb2.y; dv[6]=vb2.z; dv[7]=vb2.w;
        }
        // effective weights, padded layout: wf[((to*2+tensor)*9 + d*3+dh)*4 + dw]
        for (int idx = tid; idx < WFSZ; idx += 72) {
            int g = idx >> 2, dw = idx & 3;
            int to = g / 18, r2 = g % 18;
            int tensor = r2 / 9, qd = r2 % 9;
            int d = qd / 3, dh = qd % 3;
            int j = d * 9 + dh * 3 + dw;
            float val = 0.f;
            if (dw < 3) {
                int tt = t + to;
                float a0 = g_alpha[(b * M_ + 0) * T_ + tt];
                float a1 = g_alpha[(b * M_ + 1) * T_ + tt];
                float a2 = g_alpha[(b * M_ + 2) * T_ + tt];
                const float* Wc = tensor ? Wvc : Wkc;
                val = a0 * Wc[j] + a1 * Wc[C_ * 27 + j] + a2 * Wc[2 * C_ * 27 + j];
            }
            wf[idx] = val;
        }
        __syncthreads();

        float ak[2][2][4], av[2][2][4];
        #pragma unroll
        for (int i = 0; i < 2; ++i)
            #pragma unroll
            for (int r = 0; r < 2; ++r)
                #pragma unroll
                for (int wi = 0; wi < 4; ++wi) { ak[i][r][wi] = 0.f; av[i][r][wi] = 0.f; }

        #pragma unroll
        for (int si = 0; si < 4; ++si) {
            int slot = (t - 2 + si) & 3;  // -2&3=2, -1&3=3: correct mod-4
            const float* skb = sm + slot * SLICE;
            const float* svb = sm + (4 + slot) * SLICE;
            #pragma unroll
            for (int ri = 0; ri < 4; ++ri) {
                const float* rkp = skb + (h0 + ri) * RS + w0;  // aligned float4
                float4 f0 = ((const float4*)rkp)[0], f1 = ((const float4*)rkp)[1];
                float rowk[8] = {f0.x,f0.y,f0.z,f0.w,f1.x,f1.y,f1.z,f1.w};
                const float* rvp = svb + (h0 + ri) * RS + w0;
                float4 g0 = ((const float4*)rvp)[0], g1 = ((const float4*)rvp)[1];
                float rowv[8] = {g0.x,g0.y,g0.z,g0.w,g1.x,g1.y,g1.z,g1.w};
                #pragma unroll
                for (int to = 0; to < 2; ++to) {
                    int d = si - to;
                    if (d < 0 || d > 2) continue;       // compile-time after unroll
                    #pragma unroll
                    for (int r = 0; r < 2; ++r) {
                        int dh = ri - r;
                        if (dh < 0 || dh > 2) continue; // compile-time after unroll
                        float4 wk4 = *(const float4*)&wf[((to * 2 + 0) * 9 + d * 3 + dh) * 4];
                        float4 wv4 = *(const float4*)&wf[((to * 2 + 1) * 9 + d * 3 + dh) * 4];
                        float wkk[3] = {wk4.x, wk4.y, wk4.z};
                        float wvv[3] = {wv4.x, wv4.y, wv4.z};
                        #pragma unroll
                        for (int dw = 0; dw < 3; ++dw) {
                            #pragma unroll
                            for (int wi = 0; wi < 4; ++wi) {
                                ak[to][r][wi] = fmaf(wkk[dw], rowk[wi + dw], ak[to][r][wi]);
                                av[to][r][wi] = fmaf(wvv[dw], rowv[wi + dw], av[to][r][wi]);
                            }
                        }
                    }
                }
            }
        }
        #pragma unroll
        for (int to = 0; to < 2; ++to)
            #pragma unroll
            for (int r = 0; r < 2; ++r) {
                size_t off = (size_t)(t + to) * HW_ + (h0 + r) * W_ + w0;
                ((float4*)(okbase + off))[0] =
                    make_float4(ak[to][r][0], ak[to][r][1], ak[to][r][2], ak[to][r][3]);
                ((float4*)(ovbase + off))[0] =
                    make_float4(av[to][r][0], av[to][r][1], av[to][r][2], av[to][r][3]);
            }
    }
}

// ---------------------------------------------------------------------------
// Launch. inputs: 0=q 1=k 2=v 3=Wk 4=Wv 5=pre_w 6=pre_b 7=mix_w 8=mix_b
// ---------------------------------------------------------------------------
extern "C" void kernel_launch(void* const* d_in, const int* in_sizes, int n_in,
                              void* d_out, int out_size) {
    const float* q     = (const float*)d_in[0];
    const float* k     = (const float*)d_in[1];
    const float* v     = (const float*)d_in[2];
    const float* Wk    = (const float*)d_in[3];
    const float* Wv    = (const float*)d_in[4];
    const float* pre_w = (const float*)d_in[5];
    const float* pre_b = (const float*)d_in[6];
    const float* mix_w = (const float*)d_in[7];
    const float* mix_b = (const float*)d_in[8];
    float* out = (float*)d_out;

    pool_kernel<<<(B_ * C_ * T_) / 8, 256>>>((const float4*)q);
    {
        dim3 g(B_, 4);
        mix_kernel<<<g, 256>>>(pre_w, pre_b, mix_w, mix_b);
    }
    {
        dim3 g(T_ / TT, C_, B_);
        conv_kernel<<<g, 72>>>(k, v, Wk, Wv, out);
    }
}

// round 14
// speedup vs baseline: 1.3246x; 1.0613x over previous
#include <cuda_runtime.h>
#include <math.h>

#define B_ 4
#define C_ 128
#define T_ 32
#define H_ 24
#define W_ 24
#define M_ 3
#define HW_ (H_*W_)               // 576
#define NPER (B_*C_*T_*HW_)       // 9437184 elements per output tensor

// Scratch (device globals; no allocation allowed)
__device__ float g_qg[B_*T_*C_];     // [b][t][c]  pooled q
__device__ float g_alpha[B_*M_*T_];  // [b][m][t]  softmax mixture weights

// ---------------------------------------------------------------------------
// Kernel 1: spatial mean pool of q. One WARP per (b,c,t) slice. (measured 9.6us)
// ---------------------------------------------------------------------------
__global__ __launch_bounds__(256) void pool_kernel(const float4* __restrict__ q4) {
    int w = threadIdx.x >> 5, lane = threadIdx.x & 31;
    int idx = blockIdx.x * 8 + w;          // b*C*T + c*T + t
    const float4* p = q4 + (size_t)idx * 144;
    float4 a = p[lane], b4 = p[lane + 32], c4 = p[lane + 64], d4 = p[lane + 96];
    float s = a.x + a.y + a.z + a.w + b4.x + b4.y + b4.z + b4.w
            + c4.x + c4.y + c4.z + c4.w + d4.x + d4.y + d4.z + d4.w;
    if (lane < 16) {
        float4 e = p[lane + 128];
        s += e.x + e.y + e.z + e.w;
    }
    #pragma unroll
    for (int o = 16; o; o >>= 1) s += __shfl_down_sync(0xffffffffu, s, o);
    if (lane == 0) {
        int t = idx % T_, c = (idx / T_) % C_, b = idx / (T_ * C_);
        g_qg[(b * T_ + t) * C_ + c] = s * (1.0f / HW_);
    }
}

// ---------------------------------------------------------------------------
// Kernel 2 (measured ~5us): grid (B, 4). Each block owns 8 output timesteps,
// recomputes 2-timestep causal halo locally.
// ---------------------------------------------------------------------------
__global__ __launch_bounds__(256) void mix_kernel(const float* __restrict__ pre_w,
                                                  const float* __restrict__ pre_b,
                                                  const float* __restrict__ mix_w,
                                                  const float* __restrict__ mix_b) {
    int b = blockIdx.x, tg = blockIdx.y, tid = threadIdx.x;
    const int T0 = tg * 8;
    __shared__ float sq[10 * C_];          // qg rows T0-2..T0+7 (later: partials)
    __shared__ float sh[10 * C_];          // GELU output rows
    __shared__ float wsm[M_ * 3 * C_];     // mix_w transposed: [m][j][c]
    __shared__ float lg[M_ * 8];

    for (int i = tid; i < 10 * (C_ / 4); i += 256) {
        int row = i / (C_ / 4), c4i = i % (C_ / 4);
        int tt = T0 - 2 + row;
        float4 val = make_float4(0.f, 0.f, 0.f, 0.f);
        if (tt >= 0) val = ((const float4*)(g_qg + (b * T_ + tt) * C_))[c4i];
        ((float4*)sq)[i] = val;
    }
    for (int i = tid; i < M_ * C_ * 3; i += 256) {
        int m = i / (C_ * 3), r = i % (C_ * 3);
        int cc = r / 3, j = r % 3;
        wsm[(m * 3 + j) * C_ + cc] = mix_w[i];
    }
    __syncthreads();

    int o = tid & 127, grp = tid >> 7;
    float acc[10];
    #pragma unroll
    for (int i = 0; i < 10; ++i) acc[i] = 0.f;

    const float4* wrow = (const float4*)(pre_w + o * C_) + grp * 16;
    #pragma unroll 4
    for (int c4 = 0; c4 < 16; ++c4) {
        float4 wv = wrow[c4];
        int cbase = grp * 64 + c4 * 4;
        #pragma unroll
        for (int i = 0; i < 10; ++i) {
            float4 sv = *(const float4*)&sq[i * C_ + cbase];
            acc[i] = fmaf(wv.x, sv.x,
                     fmaf(wv.y, sv.y,
                     fmaf(wv.z, sv.z,
                     fmaf(wv.w, sv.w, acc[i]))));
        }
    }
    __syncthreads();
    if (grp == 1) {
        #pragma unroll
        for (int i = 0; i < 10; ++i) sq[i * C_ + o] = acc[i];
    }
    __syncthreads();
    if (grp == 0) {
        float pb = pre_b[o];
        #pragma unroll
        for (int i = 0; i < 10; ++i) {
            float x = acc[i] + sq[i * C_ + o] + pb;
            sh[i * C_ + o] = 0.5f * x * (1.0f + erff(x * 0.70710678118654752440f));
        }
    }
    __syncthreads();

    if (tid < 24) {
        int m = tid / 8, tl = tid % 8;
        float a0 = mix_b[m], a1 = 0.f, a2 = 0.f, a3 = 0.f;
        #pragma unroll
        for (int j = 0; j < 3; ++j) {
            int tt = T0 + tl - 2 + j;
            if (tt >= 0) {
                const float* hp = sh + (tl + j) * C_;
                const float* wp = wsm + (m * 3 + j) * C_;
                #pragma unroll 4
                for (int c = 0; c < C_; c += 4) {
                    a0 = fmaf(wp[c],     hp[c],     a0);
                    a1 = fmaf(wp[c + 1], hp[c + 1], a1);
                    a2 = fmaf(wp[c + 2], hp[c + 2], a2);
                    a3 = fmaf(wp[c + 3], hp[c + 3], a3);
                }
            }
        }
        lg[m * 8 + tl] = (a0 + a1) + (a2 + a3);
    }
    __syncthreads();
    if (tid < 8) {
        int t = T0 + tid;
        float l0 = lg[tid], l1 = lg[8 + tid], l2 = lg[16 + tid];
        float mx = fmaxf(l0, fmaxf(l1, l2));
        float e0 = expf(l0 - mx), e1 = expf(l1 - mx), e2 = expf(l2 - mx);
        float inv = 1.f / (e0 + e1 + e2);
        g_alpha[(b * M_ + 0) * T_ + t] = e0 * inv;
        g_alpha[(b * M_ + 1) * T_ + t] = e1 * inv;
        g_alpha[(b * M_ + 2) * T_ + t] = e2 * inv;
    }
}

// ---------------------------------------------------------------------------
// Kernel 3: fused mixture depthwise causal 3D conv for BOTH k and v.
// R9 tiling (2 rows x 4 cols x 2 timesteps per thread) PLUS:
//  - register double-buffer: next pair's k/v gmem loads issued before the FMA
//    block, consumed next iteration (hides DRAM latency behind compute)
//  - loop-invariant hoisting: W taps in registers, all 24 alphas staged in
//    smem once; in-loop wf build = 3 broadcast LDS + 3 FMA per slot.
// ---------------------------------------------------------------------------
#define TT    8
#define RS    28       // padded row stride (floats)
#define SLICE (26*RS)  // 728 floats per padded slice
#define WFSZ  144      // 2 to * 2 tensors * 9 (d,dh) * 4 (dw padded)

__global__ __launch_bounds__(72) void conv_kernel(
    const float* __restrict__ kin, const float* __restrict__ vin,
    const float* __restrict__ Wk,  const float* __restrict__ Wv,
    float* __restrict__ out) {
    __shared__ float sm[8 * SLICE + WFSZ + 32];  // slices + wf + alphas
    float* wf  = sm + 8 * SLICE;
    float* asm_ = wf + WFSZ;                     // alphas [m][8] (24 used)

    int t0 = blockIdx.x * TT;
    int c = blockIdx.y, b = blockIdx.z;
    int tid = threadIdx.x;
    int hi = tid / 6, seg = tid % 6;
    int h0 = hi * 2, w0 = seg * 4;
    int lrow = tid / 3, lcol = (tid % 3) * 8;

    size_t bc = (size_t)b * C_ + c;
    const float* kbase = kin + bc * T_ * HW_;
    const float* vbase = vin + bc * T_ * HW_;
    float* okbase = out + bc * T_ * HW_;
    float* ovbase = out + (size_t)NPER + bc * T_ * HW_;
    const float* Wkc = Wk + c * 27;
    const float* Wvc = Wv + c * 27;

    // ---- hoist W taps for this thread's two wf slots (idx=tid, tid+72) ----
    // decode: g=idx>>2, dw=idx&3; to=g/18; tensor=(g%18)/9; qd=g%9; j=qd/3*9+(qd%3)*3+dw
    float wA0 = 0.f, wA1 = 0.f, wA2 = 0.f, wB0 = 0.f, wB1 = 0.f, wB2 = 0.f;
    int toA, toB;
    {
        int idx = tid;
        int g = idx >> 2, dw = idx & 3;
        toA = g / 18;
        int r2 = g % 18, tensor = r2 / 9, qd = r2 % 9;
        int j = (qd / 3) * 9 + (qd % 3) * 3 + dw;
        if (dw < 3) {
            const float* Wc = tensor ? Wvc : Wkc;
            wA0 = Wc[j]; wA1 = Wc[C_ * 27 + j]; wA2 = Wc[2 * C_ * 27 + j];
        }
        idx = tid + 72;
        g = idx >> 2; dw = idx & 3;
        toB = g / 18;
        r2 = g % 18; tensor = r2 / 9; qd = r2 % 9;
        j = (qd / 3) * 9 + (qd % 3) * 3 + dw;
        if (dw < 3) {
            const float* Wc = tensor ? Wvc : Wkc;
            wB0 = Wc[j]; wB1 = Wc[C_ * 27 + j]; wB2 = Wc[2 * C_ * 27 + j];
        }
    }

    // zero all slices (borders + temporal zero padding)
    for (int i = tid; i < (8 * SLICE) / 4; i += 72)
        ((float4*)sm)[i] = make_float4(0.f, 0.f, 0.f, 0.f);
    // stage alphas for this block's 8 timesteps
    if (tid < 24) {
        int m = tid / 8, tl = tid % 8;
        asm_[m * 8 + tl] = g_alpha[(b * M_ + m) * T_ + t0 + tl];
    }
    __syncthreads();   // zeros + alphas visible

    // halo slices t0-2, t0-1 (straight to smem; only first iter depends)
    #pragma unroll
    for (int s = 0; s < 2; ++s) {
        int tt = t0 - 2 + s;
        if (tt >= 0) {
            int slot = tt & 3;
            const float* gk = kbase + (size_t)tt * HW_ + tid * 8;
            const float* gv = vbase + (size_t)tt * HW_ + tid * 8;
            float4 ka = ((const float4*)gk)[0], kb2 = ((const float4*)gk)[1];
            float4 va = ((const float4*)gv)[0], vb2 = ((const float4*)gv)[1];
            float* dk = sm + slot * SLICE + (lrow + 1) * RS + lcol + 1;
            float* dv = sm + (4 + slot) * SLICE + (lrow + 1) * RS + lcol + 1;
            dk[0]=ka.x; dk[1]=ka.y; dk[2]=ka.z; dk[3]=ka.w;
            dk[4]=kb2.x; dk[5]=kb2.y; dk[6]=kb2.z; dk[7]=kb2.w;
            dv[0]=va.x; dv[1]=va.y; dv[2]=va.z; dv[3]=va.w;
            dv[4]=vb2.x; dv[5]=vb2.y; dv[6]=vb2.z; dv[7]=vb2.w;
        }
    }

    // prefetch first body pair (t0, t0+1) into registers
    float4 pk[2][2], pv[2][2];
    #pragma unroll
    for (int s = 0; s < 2; ++s) {
        const float* gk = kbase + (size_t)(t0 + s) * HW_ + tid * 8;
        const float* gv = vbase + (size_t)(t0 + s) * HW_ + tid * 8;
        pk[s][0] = ((const float4*)gk)[0]; pk[s][1] = ((const float4*)gk)[1];
        pv[s][0] = ((const float4*)gv)[0]; pv[s][1] = ((const float4*)gv)[1];
    }

    #pragma unroll 1
    for (int p = 0; p < TT / 2; ++p) {
        int t = t0 + 2 * p;
        __syncthreads();   // previous iter's reads done before slot overwrite
        // STS prefetched pair into slots t&3, (t+1)&3
        #pragma unroll
        for (int s = 0; s < 2; ++s) {
            int slot = (t + s) & 3;
            float* dk = sm + slot * SLICE + (lrow + 1) * RS + lcol + 1;
            float* dv = sm + (4 + slot) * SLICE + (lrow + 1) * RS + lcol + 1;
            dk[0]=pk[s][0].x; dk[1]=pk[s][0].y; dk[2]=pk[s][0].z; dk[3]=pk[s][0].w;
            dk[4]=pk[s][1].x; dk[5]=pk[s][1].y; dk[6]=pk[s][1].z; dk[7]=pk[s][1].w;
            dv[0]=pv[s][0].x; dv[1]=pv[s][0].y; dv[2]=pv[s][0].z; dv[3]=pv[s][0].w;
            dv[4]=pv[s][1].x; dv[5]=pv[s][1].y; dv[6]=pv[s][1].z; dv[7]=pv[s][1].w;
        }
        // wf from hoisted W regs + smem alphas (3 broadcast LDS + 3 FMA each)
        {
            int oA = 2 * p + toA, oB = 2 * p + toB;
            wf[tid]      = wA0 * asm_[oA] + wA1 * asm_[8 + oA] + wA2 * asm_[16 + oA];
            wf[tid + 72] = wB0 * asm_[oB] + wB1 * asm_[8 + oB] + wB2 * asm_[16 + oB];
        }
        __syncthreads();

        // prefetch NEXT pair now; latency overlaps the FMA block below
        if (p < TT / 2 - 1) {
            #pragma unroll
            for (int s = 0; s < 2; ++s) {
                const float* gk = kbase + (size_t)(t + 2 + s) * HW_ + tid * 8;
                const float* gv = vbase + (size_t)(t + 2 + s) * HW_ + tid * 8;
                pk[s][0] = ((const float4*)gk)[0]; pk[s][1] = ((const float4*)gk)[1];
                pv[s][0] = ((const float4*)gv)[0]; pv[s][1] = ((const float4*)gv)[1];
            }
        }

        float ak[2][2][4], av[2][2][4];
        #pragma unroll
        for (int i = 0; i < 2; ++i)
            #pragma unroll
            for (int r = 0; r < 2; ++r)
                #pragma unroll
                for (int wi = 0; wi < 4; ++wi) { ak[i][r][wi] = 0.f; av[i][r][wi] = 0.f; }

        #pragma unroll
        for (int si = 0; si < 4; ++si) {
            int slot = (t - 2 + si) & 3;
            const float* skb = sm + slot * SLICE;
            const float* svb = sm + (4 + slot) * SLICE;
            #pragma unroll
            for (int ri = 0; ri < 4; ++ri) {
                const float* rkp = skb + (h0 + ri) * RS + w0;
                float4 f0 = ((const float4*)rkp)[0], f1 = ((const float4*)rkp)[1];
                float rowk[8] = {f0.x,f0.y,f0.z,f0.w,f1.x,f1.y,f1.z,f1.w};
                const float* rvp = svb + (h0 + ri) * RS + w0;
                float4 g0 = ((const float4*)rvp)[0], g1 = ((const float4*)rvp)[1];
                float rowv[8] = {g0.x,g0.y,g0.z,g0.w,g1.x,g1.y,g1.z,g1.w};
                #pragma unroll
                for (int to = 0; to < 2; ++to) {
                    int d = si - to;
                    if (d < 0 || d > 2) continue;
                    #pragma unroll
                    for (int r = 0; r < 2; ++r) {
                        int dh = ri - r;
                        if (dh < 0 || dh > 2) continue;
                        float4 wk4 = *(const float4*)&wf[((to * 2 + 0) * 9 + d * 3 + dh) * 4];
                        float4 wv4 = *(const float4*)&wf[((to * 2 + 1) * 9 + d * 3 + dh) * 4];
                        float wkk[3] = {wk4.x, wk4.y, wk4.z};
                        float wvv[3] = {wv4.x, wv4.y, wv4.z};
                        #pragma unroll
                        for (int dw = 0; dw < 3; ++dw) {
                            #pragma unroll
                            for (int wi = 0; wi < 4; ++wi) {
                                ak[to][r][wi] = fmaf(wkk[dw], rowk[wi + dw], ak[to][r][wi]);
                                av[to][r][wi] = fmaf(wvv[dw], rowv[wi + dw], av[to][r][wi]);
                            }
                        }
                    }
                }
            }
        }
        #pragma unroll
        for (int to = 0; to < 2; ++to)
            #pragma unroll
            for (int r = 0; r < 2; ++r) {
                size_t off = (size_t)(t + to) * HW_ + (h0 + r) * W_ + w0;
                ((float4*)(okbase + off))[0] =
                    make_float4(ak[to][r][0], ak[to][r][1], ak[to][r][2], ak[to][r][3]);
                ((float4*)(ovbase + off))[0] =
                    make_float4(av[to][r][0], av[to][r][1], av[to][r][2], av[to][r][3]);
            }
    }
}

// ---------------------------------------------------------------------------
// Launch. inputs: 0=q 1=k 2=v 3=Wk 4=Wv 5=pre_w 6=pre_b 7=mix_w 8=mix_b
// ---------------------------------------------------------------------------
extern "C" void kernel_launch(void* const* d_in, const int* in_sizes, int n_in,
                              void* d_out, int out_size) {
    const float* q     = (const float*)d_in[0];
    const float* k     = (const float*)d_in[1];
    const float* v     = (const float*)d_in[2];
    const float* Wk    = (const float*)d_in[3];
    const float* Wv    = (const float*)d_in[4];
    const float* pre_w = (const float*)d_in[5];
    const float* pre_b = (const float*)d_in[6];
    const float* mix_w = (const float*)d_in[7];
    const float* mix_b = (const float*)d_in[8];
    float* out = (float*)d_out;

    pool_kernel<<<(B_ * C_ * T_) / 8, 256>>>((const float4*)q);
    {
        dim3 g(B_, 4);
        mix_kernel<<<g, 256>>>(pre_w, pre_b, mix_w, mix_b);
    }
    {
        dim3 g(T_ / TT, C_, B_);
        conv_kernel<<<g, 72>>>(k, v, Wk, Wv, out);
    }
}